// round 14
// baseline (speedup 1.0000x reference)
#include <cuda_runtime.h>
#include <cuda_bf16.h>
#include <math.h>
#include <stdint.h>

// ---------------- problem constants ----------------
#define NB   2
#define CH   256
#define INC  128
#define ITC  16
#define NPT  32
#define HL   64
#define WL   64
#define NPIX 4096
#define HH   32
#define WH   32
#define MTOT (NB * NPIX)   // 8192 rows (batch folded into M)

// kv row layout: [v 128 bf16 | k 16 bf16 | pad 48] = 192 bf16 = 384 B (128B-aligned rows)
#define KVROW 192

// ---------------- scratch (__device__ globals, no allocs) ----------------
__device__ __align__(16) __nv_bfloat16 g_c1h[MTOT * 512];  // cat1 hi
__device__ __align__(16) __nv_bfloat16 g_c1l[MTOT * 512];  // cat1 lo
__device__ __align__(16) __nv_bfloat16 g_fh [MTOT * 256];  // qf|vf hi
__device__ __align__(16) __nv_bfloat16 g_fl [MTOT * 256];  // qf|vf lo
__device__ __align__(16) float g_qoff[MTOT * 80];          // q[16] | off[64] fp32
__device__ __align__(128) __nv_bfloat16 g_kvb[MTOT * KVROW]; // v|k bf16, 384B rows
__device__ __align__(16) __nv_bfloat16 g_attn_h[MTOT * 128];
__device__ __align__(16) __nv_bfloat16 g_attn_l[MTOT * 128];
__device__ __align__(16) __nv_bfloat16 g_W1h[128 * 512], g_W1l[128 * 512];
__device__ __align__(16) __nv_bfloat16 g_W2h[128 * 256], g_W2l[128 * 256];
__device__ __align__(16) __nv_bfloat16 g_Wbh[256 * 384], g_Wbl[256 * 384];
__device__ __align__(16) __nv_bfloat16 g_Wgh[256 * 256], g_Wgl[256 * 256];  // block-diag [q;off;k;v]
__device__ float g_bg[256];

// ---------------- mma.sync helpers ----------------
__device__ __forceinline__ uint32_t smem_u32(const void* p) {
    uint32_t a;
    asm("{ .reg .u64 t; cvta.to.shared.u64 t, %1; cvt.u32.u64 %0, t; }" : "=r"(a) : "l"(p));
    return a;
}
__device__ __forceinline__ void ldm_x4(uint32_t* r, uint32_t addr) {
    asm volatile("ldmatrix.sync.aligned.m8n8.x4.shared.b16 {%0,%1,%2,%3}, [%4];"
        : "=r"(r[0]), "=r"(r[1]), "=r"(r[2]), "=r"(r[3]) : "r"(addr));
}
__device__ __forceinline__ void mma_bf16(float* d, const uint32_t* a, const uint32_t* b) {
    asm volatile("mma.sync.aligned.m16n8k16.row.col.f32.bf16.bf16.f32 "
        "{%0,%1,%2,%3}, {%4,%5,%6,%7}, {%8,%9}, {%0,%1,%2,%3};"
        : "+f"(d[0]), "+f"(d[1]), "+f"(d[2]), "+f"(d[3])
        : "r"(a[0]), "r"(a[1]), "r"(a[2]), "r"(a[3]), "r"(b[0]), "r"(b[1]));
}

__device__ __forceinline__ void split_bf16(float x, __nv_bfloat16& h, __nv_bfloat16& l) {
    h = __float2bfloat16(x);
    l = __float2bfloat16(x - __bfloat162float(h));
}
// bf16x2 word -> two fp32 via pure bit ops (exact; no CVT pipe)
__device__ __forceinline__ float bfu_lo(uint32_t u) { return __uint_as_float(u << 16); }
__device__ __forceinline__ float bfu_hi(uint32_t u) { return __uint_as_float(u & 0xffff0000u); }
// packed bf16x2 fma: d += a*b (HFMA2.BF16_V2, fma pipe)
__device__ __forceinline__ void hfma2b(uint32_t& d, uint32_t a, uint32_t b) {
    asm("fma.rn.bf16x2 %0, %1, %2, %0;" : "+r"(d) : "r"(a), "r"(b));
}
// duplicate fp32 into both lanes of a bf16x2 word
__device__ __forceinline__ uint32_t bf16x2_dup(float x) {
    uint32_t r;
    asm("cvt.rn.bf16x2.f32 %0, %1, %1;" : "=r"(r) : "f"(x));
    return r;
}

// ---------------- prep: upsample + transpose -> bf16 splits; weight packing --
__global__ void __launch_bounds__(256) prep_kernel(
    const float* __restrict__ high, const float* __restrict__ low,
    const float* __restrict__ W1, const float* __restrict__ W2,
    const float* __restrict__ Wb,
    const float* __restrict__ Wq, const float* __restrict__ bq,
    const float* __restrict__ Woff, const float* __restrict__ boff,
    const float* __restrict__ Wk, const float* __restrict__ bk,
    const float* __restrict__ Wv, const float* __restrict__ bv)
{
    int blk = blockIdx.x;
    int tid = threadIdx.x;

    if (blk >= 4096) {
        for (int e = (blk - 4096) * 256 + tid; e < 262400; e += 16384) {
            if (e < 65536) {
                split_bf16(W1[e], g_W1h[e], g_W1l[e]);
            } else if (e < 98304) {
                int t = e - 65536;
                split_bf16(W2[t], g_W2h[t], g_W2l[t]);
            } else if (e < 196608) {
                int t = e - 98304;
                split_bf16(Wb[t], g_Wbh[t], g_Wbl[t]);
            } else if (e < 262144) {
                int t = e - 196608;
                int r = t >> 8, k = t & 255;
                float v = 0.f;
                if (r < 16)       { if (k < 128)  v = Wq[r * 128 + k]; }
                else if (r < 80)  { if (k < 128)  v = Woff[(r - 16) * 128 + k]; }
                else if (r < 96)  { if (k >= 128) v = Wk[(r - 80) * 128 + k - 128]; }
                else if (r < 224) { if (k >= 128) v = Wv[(r - 96) * 128 + k - 128]; }
                split_bf16(v, g_Wgh[t], g_Wgl[t]);
            } else {
                int i = e - 262144;
                float v = 0.f;
                if (i < 16)       v = bq[i];
                else if (i < 80)  v = boff[i - 16];
                else if (i < 96)  v = bk[i - 80];
                else if (i < 224) v = bv[i - 96];
                g_bg[i] = v;
            }
        }
        return;
    }

    int part = blk >> 11;          // 0: high_up, 1: low
    int r = blk & 2047;
    int b = r >> 10;
    int r2 = r & 1023;
    int pt = r2 >> 3;
    int ct = r2 & 7;
    int p0 = pt * 32;
    int c0 = ct * 32;

    __shared__ float s[32][33];
    int px = tid & 31;
    int cq = tid >> 5;

    if (part == 1) {
        #pragma unroll
        for (int i = 0; i < 4; i++) {
            int c = cq * 4 + i;
            s[c][px] = low[((size_t)(b * CH + c0 + c)) * NPIX + p0 + px];
        }
    } else {
        int y = p0 >> 6;
        int xb = p0 & 63;
        float fy = y * 0.5f - 0.25f;
        float y0f = floorf(fy);
        float wy = fy - y0f;
        int iy0 = min(max((int)y0f, 0), HH - 1);
        int iy1 = min(max((int)y0f + 1, 0), HH - 1);
        int x = xb + px;
        float fx = x * 0.5f - 0.25f;
        float x0f = floorf(fx);
        float wx = fx - x0f;
        int ix0 = min(max((int)x0f, 0), WH - 1);
        int ix1 = min(max((int)x0f + 1, 0), WH - 1);
        #pragma unroll
        for (int i = 0; i < 4; i++) {
            int c = cq * 4 + i;
            const float* src = high + ((size_t)(b * CH + c0 + c)) * (HH * WH);
            float v00 = src[iy0 * WH + ix0], v01 = src[iy0 * WH + ix1];
            float v10 = src[iy1 * WH + ix0], v11 = src[iy1 * WH + ix1];
            s[c][px] = (1.f - wx) * (1.f - wy) * v00 + wx * (1.f - wy) * v01
                     + (1.f - wx) * wy * v10 + wx * wy * v11;
        }
    }
    __syncthreads();

    // write out: 2 channels per store (bf16x2)
    int cc = (tid & 15) * 2;      // channel pair
    int pq = tid >> 4;            // 0..15 (2 pixels each)
    int base_c = (part == 0 ? c0 : 256 + c0) + cc;
    #pragma unroll
    for (int i = 0; i < 2; i++) {
        int pp = pq * 2 + i;
        size_t idx = ((size_t)(b * NPIX + p0 + pp)) * 512 + base_c;
        __nv_bfloat16 h0, l0, h1, l1;
        split_bf16(s[cc][pp],     h0, l0);
        split_bf16(s[cc + 1][pp], h1, l1);
        __nv_bfloat162 hp = {h0, h1}, lp = {l0, l1};
        *(__nv_bfloat162*)&g_c1h[idx] = hp;
        *(__nv_bfloat162*)&g_c1l[idx] = lp;
    }
}

// ---------------- bf16x3 mma.sync GEMM (stages 0,1,2) --------------------
// Block 64(M) x 128(N), 8 warps (2x4), warp tile 32x32, K-chunk 32,
// double-buffered smem (60KB -> 2 blocks/SM), pitch 40 bf16.  (R11 config)
#define PITCH 40
#define A_ELEMS (64 * PITCH)
#define B_ELEMS (128 * PITCH)
#define BUF_ELEMS (2 * A_ELEMS + 2 * B_ELEMS)   // 15360 elems = 30720 B
#define HMMA_SMEM_BYTES (2 * BUF_ELEMS * 2)     // 61440 B

__global__ void __launch_bounds__(256) hmma_kernel(
    int stage,
    const float* __restrict__ bias0, const float* __restrict__ bias1,
    const float* __restrict__ gamma, const float* __restrict__ beta,
    const float* __restrict__ rmean, const float* __restrict__ rvar,
    float* __restrict__ out)
{
    extern __shared__ __nv_bfloat16 sm[];
    int tid = threadIdx.x;
    int wid = tid >> 5, lane = tid & 31;
    int wm = wid >> 2, wn = wid & 3;       // 2 x 4 warp grid, warp tile 32x32
    int gid = lane >> 2, tg = lane & 3;
    int m0 = blockIdx.x * 64;
    int by = blockIdx.y;

    int K, ldb;
    const __nv_bfloat16 *Bh, *Bl;
    const float* bias = nullptr;
    if (stage == 0) {
        if (by == 0) { K = 512; Bh = g_W1h; Bl = g_W1l; ldb = 512; bias = bias0; }
        else         { K = 256; Bh = g_W2h; Bl = g_W2l; ldb = 256; bias = bias1; }
    } else if (stage == 1) {
        K = 256; ldb = 256;
        Bh = g_Wgh + (size_t)by * 128 * 256;
        Bl = g_Wgl + (size_t)by * 128 * 256;
    } else {
        K = 384; ldb = 384;
        Bh = g_Wbh + (size_t)by * 128 * 384;
        Bl = g_Wbl + (size_t)by * 128 * 384;
    }
    int nc = K >> 5;

    float d[2][4][4];
    #pragma unroll
    for (int i = 0; i < 2; i++)
        #pragma unroll
        for (int j = 0; j < 4; j++)
            #pragma unroll
            for (int k = 0; k < 4; k++) d[i][j][k] = 0.f;

    int seg = tid & 3;
    int r0 = tid >> 2;         // 0..63

    uint4 stg[6];
    auto ldg_chunk = [&](int c) {
        const __nv_bfloat16 *Ah_src, *Al_src;
        int lda, colA;
        if (stage == 0)      { Ah_src = g_c1h; Al_src = g_c1l; lda = 512; colA = c * 32; }
        else if (stage == 1) { Ah_src = g_fh;  Al_src = g_fl;  lda = 256; colA = c * 32; }
        else if (c < 4)      { Ah_src = g_attn_h; Al_src = g_attn_l; lda = 128; colA = c * 32; }
        else                 { Ah_src = g_c1h; Al_src = g_c1l; lda = 512; colA = (c - 4) * 32; }
        stg[0] = *(const uint4*)(Ah_src + (size_t)(m0 + r0) * lda + colA + seg * 8);
        stg[1] = *(const uint4*)(Al_src + (size_t)(m0 + r0) * lda + colA + seg * 8);
        stg[2] = *(const uint4*)(Bh + (size_t)r0 * ldb + c * 32 + seg * 8);
        stg[3] = *(const uint4*)(Bh + (size_t)(r0 + 64) * ldb + c * 32 + seg * 8);
        stg[4] = *(const uint4*)(Bl + (size_t)r0 * ldb + c * 32 + seg * 8);
        stg[5] = *(const uint4*)(Bl + (size_t)(r0 + 64) * ldb + c * 32 + seg * 8);
    };
    auto sts_chunk = [&](int buf) {
        __nv_bfloat16* base = sm + buf * BUF_ELEMS;
        *(uint4*)(base + r0 * PITCH + seg * 8)                          = stg[0];
        *(uint4*)(base + A_ELEMS + r0 * PITCH + seg * 8)                = stg[1];
        *(uint4*)(base + 2 * A_ELEMS + r0 * PITCH + seg * 8)            = stg[2];
        *(uint4*)(base + 2 * A_ELEMS + (r0 + 64) * PITCH + seg * 8)     = stg[3];
        *(uint4*)(base + 2 * A_ELEMS + B_ELEMS + r0 * PITCH + seg * 8)  = stg[4];
        *(uint4*)(base + 2 * A_ELEMS + B_ELEMS + (r0 + 64) * PITCH + seg * 8) = stg[5];
    };

    uint32_t sm0 = smem_u32(sm);
    auto compute = [&](int buf) {
        uint32_t aAh = sm0 + (buf * BUF_ELEMS) * 2;
        uint32_t aAl = aAh + A_ELEMS * 2;
        uint32_t aBh = aAl + A_ELEMS * 2;
        uint32_t aBl = aBh + B_ELEMS * 2;
        #pragma unroll
        for (int h = 0; h < 2; h++) {
            uint32_t ah[2][4], al[2][4], bh[2][4], bl[2][4];
            uint32_t a_off = (uint32_t)((wm * 32 + (lane & 15)) * (PITCH * 2)
                                        + h * 32 + (lane >> 4) * 16);
            #pragma unroll
            for (int mt = 0; mt < 2; mt++) {
                ldm_x4(ah[mt], aAh + a_off + mt * 16 * (PITCH * 2));
                ldm_x4(al[mt], aAl + a_off + mt * 16 * (PITCH * 2));
            }
            int q8 = lane >> 3;
            uint32_t b_off = (uint32_t)((wn * 32 + (q8 >> 1) * 8 + (lane & 7)) * (PITCH * 2)
                                        + h * 32 + (q8 & 1) * 16);
            ldm_x4(bh[0], aBh + b_off);
            ldm_x4(bh[1], aBh + b_off + 16 * (PITCH * 2));
            ldm_x4(bl[0], aBl + b_off);
            ldm_x4(bl[1], aBl + b_off + 16 * (PITCH * 2));
            #pragma unroll
            for (int mt = 0; mt < 2; mt++) {
                #pragma unroll
                for (int nt = 0; nt < 4; nt++) {
                    const uint32_t* pbh = &bh[nt >> 1][(nt & 1) * 2];
                    const uint32_t* pbl = &bl[nt >> 1][(nt & 1) * 2];
                    mma_bf16(d[mt][nt], ah[mt], pbh);
                    mma_bf16(d[mt][nt], ah[mt], pbl);
                    mma_bf16(d[mt][nt], al[mt], pbh);
                }
            }
        }
    };

    ldg_chunk(0);
    sts_chunk(0);
    __syncthreads();
    for (int c = 0; c < nc; c++) {
        if (c + 1 < nc) ldg_chunk(c + 1);
        compute(c & 1);
        if (c + 1 < nc) {
            sts_chunk((c + 1) & 1);
            __syncthreads();
        }
    }

    if (stage == 0) {
        #pragma unroll
        for (int mt = 0; mt < 2; mt++) {
            int m = m0 + wm * 32 + mt * 16 + gid;
            #pragma unroll
            for (int nt = 0; nt < 4; nt++) {
                int cc = wn * 32 + nt * 8 + tg * 2;
                int gcol = by * 128 + cc;
                float bx = bias[cc], byv = bias[cc + 1];
                float v00 = d[mt][nt][0] + bx, v01 = d[mt][nt][1] + byv;
                float v10 = d[mt][nt][2] + bx, v11 = d[mt][nt][3] + byv;
                __nv_bfloat16 h0, l0, h1, l1;
                split_bf16(v00, h0, l0); split_bf16(v01, h1, l1);
                __nv_bfloat162 hp0 = {h0, h1}, lp0 = {l0, l1};
                split_bf16(v10, h0, l0); split_bf16(v11, h1, l1);
                __nv_bfloat162 hp1 = {h0, h1}, lp1 = {l0, l1};
                *(__nv_bfloat162*)&g_fh[(size_t)m * 256 + gcol] = hp0;
                *(__nv_bfloat162*)&g_fl[(size_t)m * 256 + gcol] = lp0;
                *(__nv_bfloat162*)&g_fh[(size_t)(m + 8) * 256 + gcol] = hp1;
                *(__nv_bfloat162*)&g_fl[(size_t)(m + 8) * 256 + gcol] = lp1;
            }
        }
    } else if (stage == 1) {
        // q|off fp32 -> g_qoff; k -> kv row offset 128+, v -> offset 0+ (bf16)
        #pragma unroll
        for (int mt = 0; mt < 2; mt++) {
            int m = m0 + wm * 32 + mt * 16 + gid;
            #pragma unroll
            for (int nt = 0; nt < 4; nt++) {
                int gc = by * 128 + wn * 32 + nt * 8 + tg * 2;
                if (gc >= 224) continue;
                float bx = g_bg[gc], byv = g_bg[gc + 1];
                float2 lo = make_float2(d[mt][nt][0] + bx, d[mt][nt][1] + byv);
                float2 hi = make_float2(d[mt][nt][2] + bx, d[mt][nt][3] + byv);
                if (gc < 80) {
                    *(float2*)(g_qoff + (size_t)m * 80 + gc) = lo;
                    *(float2*)(g_qoff + (size_t)(m + 8) * 80 + gc) = hi;
                } else {
                    int off = (gc < 96) ? (128 + gc - 80) : (gc - 96);
                    __nv_bfloat162 blo = __float22bfloat162_rn(lo);
                    __nv_bfloat162 bhi = __float22bfloat162_rn(hi);
                    *(__nv_bfloat162*)(g_kvb + (size_t)m * KVROW + off) = blo;
                    *(__nv_bfloat162*)(g_kvb + (size_t)(m + 8) * KVROW + off) = bhi;
                }
            }
        }
    } else {
        int bidx = m0 >> 12;
        int pixbase = (m0 & 4095) + wm * 32;
        #pragma unroll
        for (int nt = 0; nt < 4; nt++) {
            int oc = by * 128 + wn * 32 + nt * 8 + tg * 2;
            float inv0 = rsqrtf(rvar[oc] + 1e-5f);
            float sc0 = gamma[oc] * inv0;
            float sh0 = beta[oc] - rmean[oc] * sc0;
            float inv1 = rsqrtf(rvar[oc + 1] + 1e-5f);
            float sc1 = gamma[oc + 1] * inv1;
            float sh1 = beta[oc + 1] - rmean[oc + 1] * sc1;
            float* o0 = out + ((size_t)(bidx * 256 + oc)) * NPIX;
            float* o1 = out + ((size_t)(bidx * 256 + oc + 1)) * NPIX;
            #pragma unroll
            for (int mt = 0; mt < 2; mt++) {
                int pix = pixbase + mt * 16 + gid;
                o0[pix]     = fmaxf(d[mt][nt][0] * sc0 + sh0, 0.f);
                o1[pix]     = fmaxf(d[mt][nt][1] * sc1 + sh1, 0.f);
                o0[pix + 8] = fmaxf(d[mt][nt][2] * sc0 + sh0, 0.f);
                o1[pix + 8] = fmaxf(d[mt][nt][3] * sc1 + sh1, 0.f);
            }
        }
    }
}

// ---------------- deformable point attention (2 warps / query, bf16 kv,
//                   packed-HFMA2 phase 2, 128B-aligned v rows) ------------
__global__ void __launch_bounds__(512, 3) attention_kernel()
{
    __shared__ int    sIdx[8][128];
    __shared__ float  sW  [8][128];     // phase1: float weight; after fold: bf16x2-dup (uint)
    __shared__ float  sLogit[8][32];
    __shared__ float  sAttn[8][32];
    __shared__ float4 sPart[8][32];
    int tid = threadIdx.x;
    int warp = tid >> 5, lane = tid & 31;
    int q = warp & 7, half = warp >> 3;
    int m = blockIdx.x * 8 + q;
    int b = m >> 12;
    int n = m & (NPIX - 1);

    const float* row = g_qoff + (size_t)m * 80;

    // per-lane (point = lane) offsets -> 4 taps
    float2 d = *(const float2*)(row + 16 + 2 * lane);
    float sx = (float)(n & 63) + d.x;
    float sy = (float)(n >> 6) + d.y;
    float x0f = floorf(sx), y0f = floorf(sy);
    float wx = sx - x0f,    wy = sy - y0f;
    int ix0 = min(max((int)x0f, 0), WL - 1);
    int ix1 = min(max((int)x0f + 1, 0), WL - 1);
    int iy0 = min(max((int)y0f, 0), HL - 1);
    int iy1 = min(max((int)y0f + 1, 0), HL - 1);
    // tap indices in BYTES (row = 192 bf16 = 384 B, 128B-aligned)
    int g00 = (iy0 * WL + ix0) * 384, g01 = (iy0 * WL + ix1) * 384;
    int g10 = (iy1 * WL + ix0) * 384, g11 = (iy1 * WL + ix1) * 384;
    float w00 = (1.f - wx) * (1.f - wy), w01 = wx * (1.f - wy);
    float w10 = (1.f - wx) * wy,         w11 = wx * wy;

    int cq = lane & 3;
    int oct = lane >> 2;
    float4 qv = *(const float4*)(row + 4 * cq);
    const char* kvB = (const char*)(g_kvb + (size_t)b * NPIX * KVROW);

    // phase 1: this warp handles point groups {half*2, half*2+1}; k at byte 256
    #pragma unroll
    for (int gi = 0; gi < 2; gi++) {
        int g = half * 2 + gi;
        int src = oct + 8 * g;
        int G0 = __shfl_sync(0xffffffffu, g00, src);
        int G1 = __shfl_sync(0xffffffffu, g01, src);
        int G2 = __shfl_sync(0xffffffffu, g10, src);
        int G3 = __shfl_sync(0xffffffffu, g11, src);
        float W0 = __shfl_sync(0xffffffffu, w00, src);
        float W1 = __shfl_sync(0xffffffffu, w01, src);
        float W2 = __shfl_sync(0xffffffffu, w10, src);
        float W3 = __shfl_sync(0xffffffffu, w11, src);
        uint2 kp0 = *(const uint2*)(kvB + G0 + 256 + cq * 8);
        uint2 kp1 = *(const uint2*)(kvB + G1 + 256 + cq * 8);
        uint2 kp2 = *(const uint2*)(kvB + G2 + 256 + cq * 8);
        uint2 kp3 = *(const uint2*)(kvB + G3 + 256 + cq * 8);
        float ksx = W0 * bfu_lo(kp0.x) + W1 * bfu_lo(kp1.x) + W2 * bfu_lo(kp2.x) + W3 * bfu_lo(kp3.x);
        float ksy = W0 * bfu_hi(kp0.x) + W1 * bfu_hi(kp1.x) + W2 * bfu_hi(kp2.x) + W3 * bfu_hi(kp3.x);
        float ksz = W0 * bfu_lo(kp0.y) + W1 * bfu_lo(kp1.y) + W2 * bfu_lo(kp2.y) + W3 * bfu_lo(kp3.y);
        float ksw = W0 * bfu_hi(kp0.y) + W1 * bfu_hi(kp1.y) + W2 * bfu_hi(kp2.y) + W3 * bfu_hi(kp3.y);
        float part = qv.x * ksx + qv.y * ksy + qv.z * ksz + qv.w * ksw;
        part += __shfl_xor_sync(0xffffffffu, part, 1);
        part += __shfl_xor_sync(0xffffffffu, part, 2);
        if (cq == 0) sLogit[q][src] = part * 0.25f;   // 1/sqrt(16)
        int   Gq = (cq == 0) ? G0 : (cq == 1) ? G1 : (cq == 2) ? G2 : G3;
        float Wq = (cq == 0) ? W0 : (cq == 1) ? W1 : (cq == 2) ? W2 : W3;
        sIdx[q][src * 4 + cq] = Gq;
        sW  [q][src * 4 + cq] = Wq;
    }
    __syncthreads();

    // softmax over 32 points (both pair warps compute identically)
    float lg = sLogit[q][lane];
    float mx = lg;
    #pragma unroll
    for (int s = 16; s; s >>= 1) mx = fmaxf(mx, __shfl_xor_sync(0xffffffffu, mx, s));
    float e = __expf(lg - mx);
    float sum = e;
    #pragma unroll
    for (int s = 16; s; s >>= 1) sum += __shfl_xor_sync(0xffffffffu, sum, s);
    sAttn[q][lane] = e / sum;
    __syncwarp();

    // pre-fold attn into tap weights, pack as dup'd bf16x2 (own half only)
    int base = half * 64;
    uint32_t* sWp = (uint32_t*)&sW[q][0];
    #pragma unroll
    for (int j = 0; j < 2; j++) {
        int tt = base + j * 32 + lane;
        float w = sW[q][tt] * sAttn[q][tt >> 2];
        sWp[tt] = bf16x2_dup(w);
    }
    __syncwarp();

    // phase 2: packed bf16x2 gather-accumulate; v at row offset 0, 128B-aligned
    float4 acc = make_float4(0.f, 0.f, 0.f, 0.f);
    int loff = lane * 8;
    #pragma unroll 4
    for (int t = 0; t < 64; t += 4) {
        int tt = base + t;
        int4  i4  = *(const int4*)&sIdx[q][tt];
        uint4 wp4 = *(const uint4*)&sWp[tt];
        uint2 p0 = *(const uint2*)(kvB + i4.x + loff);
        uint2 p1 = *(const uint2*)(kvB + i4.y + loff);
        uint2 p2 = *(const uint2*)(kvB + i4.z + loff);
        uint2 p3 = *(const uint2*)(kvB + i4.w + loff);
        uint32_t a0 = 0, a1 = 0;
        hfma2b(a0, wp4.x, p0.x);  hfma2b(a1, wp4.x, p0.y);
        hfma2b(a0, wp4.y, p1.x);  hfma2b(a1, wp4.y, p1.y);
        hfma2b(a0, wp4.z, p2.x);  hfma2b(a1, wp4.z, p2.y);
        hfma2b(a0, wp4.w, p3.x);  hfma2b(a1, wp4.w, p3.y);
        acc.x += bfu_lo(a0);  acc.y += bfu_hi(a0);
        acc.z += bfu_lo(a1);  acc.w += bfu_hi(a1);
    }
    if (half) sPart[q][lane] = acc;
    __syncthreads();
    if (!half) {
        float4 p = sPart[q][lane];
        acc.x += p.x; acc.y += p.y; acc.z += p.z; acc.w += p.w;
        size_t obase = (size_t)m * 128 + lane * 4;
        __nv_bfloat16 hv[4], lv[4];
        split_bf16(acc.x, hv[0], lv[0]);
        split_bf16(acc.y, hv[1], lv[1]);
        split_bf16(acc.z, hv[2], lv[2]);
        split_bf16(acc.w, hv[3], lv[3]);
        *(uint2*)&g_attn_h[obase] = *(uint2*)hv;
        *(uint2*)&g_attn_l[obase] = *(uint2*)lv;
    }
}

// ---------------- launch ------------------------------------------------
extern "C" void kernel_launch(void* const* d_in, const int* in_sizes, int n_in,
                              void* d_out, int out_size) {
    const float* low   = (const float*)d_in[0];
    const float* high  = (const float*)d_in[1];
    const float* W1    = (const float*)d_in[2];
    const float* b1    = (const float*)d_in[3];
    const float* W2    = (const float*)d_in[4];
    const float* b2    = (const float*)d_in[5];
    const float* Wq    = (const float*)d_in[6];
    const float* bq    = (const float*)d_in[7];
    const float* Wk    = (const float*)d_in[8];
    const float* bk    = (const float*)d_in[9];
    const float* Wv    = (const float*)d_in[10];
    const float* bv    = (const float*)d_in[11];
    const float* Woff  = (const float*)d_in[12];
    const float* boff  = (const float*)d_in[13];
    const float* Wb    = (const float*)d_in[14];
    const float* gamma = (const float*)d_in[15];
    const float* beta  = (const float*)d_in[16];
    const float* rmean = (const float*)d_in[17];
    const float* rvar  = (const float*)d_in[18];
    float* out = (float*)d_out;

    cudaFuncSetAttribute(hmma_kernel, cudaFuncAttributeMaxDynamicSharedMemorySize, HMMA_SMEM_BYTES);

    prep_kernel<<<4160, 256>>>(high, low, W1, W2, Wb,
                               Wq, bq, Woff, boff, Wk, bk, Wv, bv);
    hmma_kernel<<<dim3(128, 2), 256, HMMA_SMEM_BYTES>>>(
        0, b1, b2, nullptr, nullptr, nullptr, nullptr, nullptr);
    hmma_kernel<<<dim3(128, 2), 256, HMMA_SMEM_BYTES>>>(
        1, nullptr, nullptr, nullptr, nullptr, nullptr, nullptr, nullptr);
    attention_kernel<<<MTOT / 8, 512>>>();
    hmma_kernel<<<dim3(128, 2), 256, HMMA_SMEM_BYTES>>>(
        2, nullptr, nullptr, gamma, beta, rmean, rvar, out);
}

// round 15
// speedup vs baseline: 1.1348x; 1.1348x over previous
#include <cuda_runtime.h>
#include <cuda_bf16.h>
#include <math.h>
#include <stdint.h>

// ---------------- problem constants ----------------
#define NB   2
#define CH   256
#define INC  128
#define ITC  16
#define NPT  32
#define HL   64
#define WL   64
#define NPIX 4096
#define HH   32
#define WH   32
#define MTOT (NB * NPIX)   // 8192 rows (batch folded into M)

// ---------------- scratch (__device__ globals, no allocs) ----------------
__device__ __align__(16) __nv_bfloat16 g_c1h[MTOT * 512];  // cat1 hi
__device__ __align__(16) __nv_bfloat16 g_c1l[MTOT * 512];  // cat1 lo
__device__ __align__(16) __nv_bfloat16 g_fh [MTOT * 256];  // qf|vf (bf16, single)
__device__ __align__(16) float g_qoff[MTOT * 80];          // q[16] | off[64] fp32
__device__ __align__(16) __nv_bfloat16 g_kvb[MTOT * 144];  // k[16] | v[128] bf16 (288B rows)
__device__ __align__(16) __nv_bfloat16 g_attn_h[MTOT * 128];
__device__ __align__(16) __nv_bfloat16 g_attn_l[MTOT * 128];
__device__ __align__(16) __nv_bfloat16 g_W1h[128 * 512];
__device__ __align__(16) __nv_bfloat16 g_W2h[128 * 256];
__device__ __align__(16) __nv_bfloat16 g_Wbh[256 * 384], g_Wbl[256 * 384];
__device__ __align__(16) __nv_bfloat16 g_Wgh[256 * 256];   // block-diag [q;off;k;v]
__device__ float g_bg[256];

// ---------------- mma.sync helpers ----------------
__device__ __forceinline__ uint32_t smem_u32(const void* p) {
    uint32_t a;
    asm("{ .reg .u64 t; cvta.to.shared.u64 t, %1; cvt.u32.u64 %0, t; }" : "=r"(a) : "l"(p));
    return a;
}
__device__ __forceinline__ void ldm_x4(uint32_t* r, uint32_t addr) {
    asm volatile("ldmatrix.sync.aligned.m8n8.x4.shared.b16 {%0,%1,%2,%3}, [%4];"
        : "=r"(r[0]), "=r"(r[1]), "=r"(r[2]), "=r"(r[3]) : "r"(addr));
}
__device__ __forceinline__ void mma_bf16(float* d, const uint32_t* a, const uint32_t* b) {
    asm volatile("mma.sync.aligned.m16n8k16.row.col.f32.bf16.bf16.f32 "
        "{%0,%1,%2,%3}, {%4,%5,%6,%7}, {%8,%9}, {%0,%1,%2,%3};"
        : "+f"(d[0]), "+f"(d[1]), "+f"(d[2]), "+f"(d[3])
        : "r"(a[0]), "r"(a[1]), "r"(a[2]), "r"(a[3]), "r"(b[0]), "r"(b[1]));
}

__device__ __forceinline__ void split_bf16(float x, __nv_bfloat16& h, __nv_bfloat16& l) {
    h = __float2bfloat16(x);
    l = __float2bfloat16(x - __bfloat162float(h));
}
// bf16x2 word -> two fp32 via pure bit ops (exact; no CVT pipe)
__device__ __forceinline__ float bfu_lo(uint32_t u) { return __uint_as_float(u << 16); }
__device__ __forceinline__ float bfu_hi(uint32_t u) { return __uint_as_float(u & 0xffff0000u); }
// packed bf16x2 fma: d += a*b (HFMA2.BF16_V2, fma pipe)
__device__ __forceinline__ void hfma2b(uint32_t& d, uint32_t a, uint32_t b) {
    asm("fma.rn.bf16x2 %0, %1, %2, %0;" : "+r"(d) : "r"(a), "r"(b));
}
// duplicate fp32 into both lanes of a bf16x2 word
__device__ __forceinline__ uint32_t bf16x2_dup(float x) {
    uint32_t r;
    asm("cvt.rn.bf16x2.f32 %0, %1, %1;" : "=r"(r) : "f"(x));
    return r;
}

// ---------------- prep: upsample + transpose -> bf16 splits; weight packing --
__global__ void __launch_bounds__(256) prep_kernel(
    const float* __restrict__ high, const float* __restrict__ low,
    const float* __restrict__ W1, const float* __restrict__ W2,
    const float* __restrict__ Wb,
    const float* __restrict__ Wq, const float* __restrict__ bq,
    const float* __restrict__ Woff, const float* __restrict__ boff,
    const float* __restrict__ Wk, const float* __restrict__ bk,
    const float* __restrict__ Wv, const float* __restrict__ bv)
{
    int blk = blockIdx.x;
    int tid = threadIdx.x;

    if (blk >= 4096) {
        for (int e = (blk - 4096) * 256 + tid; e < 262400; e += 16384) {
            if (e < 65536) {
                g_W1h[e] = __float2bfloat16(W1[e]);
            } else if (e < 98304) {
                int t = e - 65536;
                g_W2h[t] = __float2bfloat16(W2[t]);
            } else if (e < 196608) {
                int t = e - 98304;
                split_bf16(Wb[t], g_Wbh[t], g_Wbl[t]);
            } else if (e < 262144) {
                int t = e - 196608;
                int r = t >> 8, k = t & 255;
                float v = 0.f;
                if (r < 16)       { if (k < 128)  v = Wq[r * 128 + k]; }
                else if (r < 80)  { if (k < 128)  v = Woff[(r - 16) * 128 + k]; }
                else if (r < 96)  { if (k >= 128) v = Wk[(r - 80) * 128 + k - 128]; }
                else if (r < 224) { if (k >= 128) v = Wv[(r - 96) * 128 + k - 128]; }
                g_Wgh[t] = __float2bfloat16(v);
            } else {
                int i = e - 262144;
                float v = 0.f;
                if (i < 16)       v = bq[i];
                else if (i < 80)  v = boff[i - 16];
                else if (i < 96)  v = bk[i - 80];
                else if (i < 224) v = bv[i - 96];
                g_bg[i] = v;
            }
        }
        return;
    }

    int part = blk >> 11;          // 0: high_up, 1: low
    int r = blk & 2047;
    int b = r >> 10;
    int r2 = r & 1023;
    int pt = r2 >> 3;
    int ct = r2 & 7;
    int p0 = pt * 32;
    int c0 = ct * 32;

    __shared__ float s[32][33];
    int px = tid & 31;
    int cq = tid >> 5;

    if (part == 1) {
        #pragma unroll
        for (int i = 0; i < 4; i++) {
            int c = cq * 4 + i;
            s[c][px] = low[((size_t)(b * CH + c0 + c)) * NPIX + p0 + px];
        }
    } else {
        int y = p0 >> 6;
        int xb = p0 & 63;
        float fy = y * 0.5f - 0.25f;
        float y0f = floorf(fy);
        float wy = fy - y0f;
        int iy0 = min(max((int)y0f, 0), HH - 1);
        int iy1 = min(max((int)y0f + 1, 0), HH - 1);
        int x = xb + px;
        float fx = x * 0.5f - 0.25f;
        float x0f = floorf(fx);
        float wx = fx - x0f;
        int ix0 = min(max((int)x0f, 0), WH - 1);
        int ix1 = min(max((int)x0f + 1, 0), WH - 1);
        #pragma unroll
        for (int i = 0; i < 4; i++) {
            int c = cq * 4 + i;
            const float* src = high + ((size_t)(b * CH + c0 + c)) * (HH * WH);
            float v00 = src[iy0 * WH + ix0], v01 = src[iy0 * WH + ix1];
            float v10 = src[iy1 * WH + ix0], v11 = src[iy1 * WH + ix1];
            s[c][px] = (1.f - wx) * (1.f - wy) * v00 + wx * (1.f - wy) * v01
                     + (1.f - wx) * wy * v10 + wx * wy * v11;
        }
    }
    __syncthreads();

    // write out: 2 channels per store (bf16x2)
    int cc = (tid & 15) * 2;      // channel pair
    int pq = tid >> 4;            // 0..15 (2 pixels each)
    int base_c = (part == 0 ? c0 : 256 + c0) + cc;
    #pragma unroll
    for (int i = 0; i < 2; i++) {
        int pp = pq * 2 + i;
        size_t idx = ((size_t)(b * NPIX + p0 + pp)) * 512 + base_c;
        __nv_bfloat16 h0, l0, h1, l1;
        split_bf16(s[cc][pp],     h0, l0);
        split_bf16(s[cc + 1][pp], h1, l1);
        __nv_bfloat162 hp = {h0, h1}, lp = {l0, l1};
        *(__nv_bfloat162*)&g_c1h[idx] = hp;
        *(__nv_bfloat162*)&g_c1l[idx] = lp;
    }
}

// ---------------- bf16 mma.sync GEMM (stages 0,1 single-term; 2 bf16x3) --
// Block 64(M) x 128(N), 8 warps (2x4), warp tile 32x32, K-chunk 32,
// double-buffered smem, pitch 40 bf16.
#define PITCH 40
#define A_ELEMS (64 * PITCH)
#define B_ELEMS (128 * PITCH)
#define BUF1 (A_ELEMS + B_ELEMS)       // single-term buffer: 7680 elems
#define BUF2 (2 * (A_ELEMS + B_ELEMS)) // full buffer: 15360 elems
#define HMMA_SMEM_1 (2 * BUF1 * 2)     // 30720 B
#define HMMA_SMEM_2 (2 * BUF2 * 2)     // 61440 B

__global__ void __launch_bounds__(256) hmma_kernel(
    int stage,
    const float* __restrict__ bias0, const float* __restrict__ bias1,
    const float* __restrict__ gamma, const float* __restrict__ beta,
    const float* __restrict__ rmean, const float* __restrict__ rvar,
    float* __restrict__ out)
{
    extern __shared__ __nv_bfloat16 sm[];
    int tid = threadIdx.x;
    int wid = tid >> 5, lane = tid & 31;
    int wm = wid >> 2, wn = wid & 3;       // 2 x 4 warp grid, warp tile 32x32
    int gid = lane >> 2, tg = lane & 3;
    int m0 = blockIdx.x * 64;
    int by = blockIdx.y;

    bool full = (stage == 2);
    int bufElems = full ? BUF2 : BUF1;

    int K, ldb;
    const __nv_bfloat16 *Bh, *Bl = nullptr;
    const float* bias = nullptr;
    if (stage == 0) {
        if (by == 0) { K = 512; Bh = g_W1h; ldb = 512; bias = bias0; }
        else         { K = 256; Bh = g_W2h; ldb = 256; bias = bias1; }
    } else if (stage == 1) {
        K = 256; ldb = 256;
        Bh = g_Wgh + (size_t)by * 128 * 256;
    } else {
        K = 384; ldb = 384;
        Bh = g_Wbh + (size_t)by * 128 * 384;
        Bl = g_Wbl + (size_t)by * 128 * 384;
    }
    int nc = K >> 5;

    float d[2][4][4];
    #pragma unroll
    for (int i = 0; i < 2; i++)
        #pragma unroll
        for (int j = 0; j < 4; j++)
            #pragma unroll
            for (int k = 0; k < 4; k++) d[i][j][k] = 0.f;

    int seg = tid & 3;
    int r0 = tid >> 2;         // 0..63

    uint4 stg[6];
    auto ldg_chunk = [&](int c) {
        const __nv_bfloat16 *Ah_src, *Al_src = nullptr;
        int lda, colA;
        if (stage == 0)      { Ah_src = g_c1h; lda = 512; colA = c * 32; }
        else if (stage == 1) { Ah_src = g_fh;  lda = 256; colA = c * 32; }
        else if (c < 4)      { Ah_src = g_attn_h; Al_src = g_attn_l; lda = 128; colA = c * 32; }
        else                 { Ah_src = g_c1h; Al_src = g_c1l; lda = 512; colA = (c - 4) * 32; }
        stg[0] = *(const uint4*)(Ah_src + (size_t)(m0 + r0) * lda + colA + seg * 8);
        stg[1] = *(const uint4*)(Bh + (size_t)r0 * ldb + c * 32 + seg * 8);
        stg[2] = *(const uint4*)(Bh + (size_t)(r0 + 64) * ldb + c * 32 + seg * 8);
        if (full) {
            stg[3] = *(const uint4*)(Al_src + (size_t)(m0 + r0) * lda + colA + seg * 8);
            stg[4] = *(const uint4*)(Bl + (size_t)r0 * ldb + c * 32 + seg * 8);
            stg[5] = *(const uint4*)(Bl + (size_t)(r0 + 64) * ldb + c * 32 + seg * 8);
        }
    };
    // buffer layout: [Ah | Bh | (Al) | (Bl)]
    auto sts_chunk = [&](int buf) {
        __nv_bfloat16* base = sm + buf * bufElems;
        *(uint4*)(base + r0 * PITCH + seg * 8)                      = stg[0];
        *(uint4*)(base + A_ELEMS + r0 * PITCH + seg * 8)            = stg[1];
        *(uint4*)(base + A_ELEMS + (r0 + 64) * PITCH + seg * 8)     = stg[2];
        if (full) {
            __nv_bfloat16* b2 = base + A_ELEMS + B_ELEMS;
            *(uint4*)(b2 + r0 * PITCH + seg * 8)                    = stg[3];
            *(uint4*)(b2 + A_ELEMS + r0 * PITCH + seg * 8)          = stg[4];
            *(uint4*)(b2 + A_ELEMS + (r0 + 64) * PITCH + seg * 8)   = stg[5];
        }
    };

    uint32_t sm0 = smem_u32(sm);
    auto compute = [&](int buf) {
        uint32_t base = sm0 + (buf * bufElems) * 2;
        uint32_t aAh = base;
        uint32_t aBh = base + A_ELEMS * 2;
        uint32_t aAl = base + (A_ELEMS + B_ELEMS) * 2;
        uint32_t aBl = aAl + A_ELEMS * 2;
        #pragma unroll
        for (int h = 0; h < 2; h++) {
            uint32_t ah[2][4], al[2][4], bh[2][4], bl[2][4];
            uint32_t a_off = (uint32_t)((wm * 32 + (lane & 15)) * (PITCH * 2)
                                        + h * 32 + (lane >> 4) * 16);
            int q8 = lane >> 3;
            uint32_t b_off = (uint32_t)((wn * 32 + (q8 >> 1) * 8 + (lane & 7)) * (PITCH * 2)
                                        + h * 32 + (q8 & 1) * 16);
            #pragma unroll
            for (int mt = 0; mt < 2; mt++)
                ldm_x4(ah[mt], aAh + a_off + mt * 16 * (PITCH * 2));
            ldm_x4(bh[0], aBh + b_off);
            ldm_x4(bh[1], aBh + b_off + 16 * (PITCH * 2));
            if (full) {
                #pragma unroll
                for (int mt = 0; mt < 2; mt++)
                    ldm_x4(al[mt], aAl + a_off + mt * 16 * (PITCH * 2));
                ldm_x4(bl[0], aBl + b_off);
                ldm_x4(bl[1], aBl + b_off + 16 * (PITCH * 2));
            }
            #pragma unroll
            for (int mt = 0; mt < 2; mt++) {
                #pragma unroll
                for (int nt = 0; nt < 4; nt++) {
                    const uint32_t* pbh = &bh[nt >> 1][(nt & 1) * 2];
                    mma_bf16(d[mt][nt], ah[mt], pbh);
                    if (full) {
                        const uint32_t* pbl = &bl[nt >> 1][(nt & 1) * 2];
                        mma_bf16(d[mt][nt], ah[mt], pbl);
                        mma_bf16(d[mt][nt], al[mt], pbh);
                    }
                }
            }
        }
    };

    ldg_chunk(0);
    sts_chunk(0);
    __syncthreads();
    for (int c = 0; c < nc; c++) {
        if (c + 1 < nc) ldg_chunk(c + 1);
        compute(c & 1);
        if (c + 1 < nc) {
            sts_chunk((c + 1) & 1);
            __syncthreads();
        }
    }

    if (stage == 0) {
        // write bf16 (single) into g_fh [m][256] (qf cols 0-127, vf 128-255)
        #pragma unroll
        for (int mt = 0; mt < 2; mt++) {
            int m = m0 + wm * 32 + mt * 16 + gid;
            #pragma unroll
            for (int nt = 0; nt < 4; nt++) {
                int cc = wn * 32 + nt * 8 + tg * 2;
                int gcol = by * 128 + cc;
                float bx = bias[cc], byv = bias[cc + 1];
                float2 lo = make_float2(d[mt][nt][0] + bx, d[mt][nt][1] + byv);
                float2 hi = make_float2(d[mt][nt][2] + bx, d[mt][nt][3] + byv);
                *(__nv_bfloat162*)&g_fh[(size_t)m * 256 + gcol] = __float22bfloat162_rn(lo);
                *(__nv_bfloat162*)&g_fh[(size_t)(m + 8) * 256 + gcol] = __float22bfloat162_rn(hi);
            }
        }
    } else if (stage == 1) {
        // q|off fp32 -> g_qoff; k|v bf16 -> g_kvb
        #pragma unroll
        for (int mt = 0; mt < 2; mt++) {
            int m = m0 + wm * 32 + mt * 16 + gid;
            #pragma unroll
            for (int nt = 0; nt < 4; nt++) {
                int gc = by * 128 + wn * 32 + nt * 8 + tg * 2;
                if (gc >= 224) continue;
                float bx = g_bg[gc], byv = g_bg[gc + 1];
                float2 lo = make_float2(d[mt][nt][0] + bx, d[mt][nt][1] + byv);
                float2 hi = make_float2(d[mt][nt][2] + bx, d[mt][nt][3] + byv);
                if (gc < 80) {
                    *(float2*)(g_qoff + (size_t)m * 80 + gc) = lo;
                    *(float2*)(g_qoff + (size_t)(m + 8) * 80 + gc) = hi;
                } else {
                    __nv_bfloat162 blo = __float22bfloat162_rn(lo);
                    __nv_bfloat162 bhi = __float22bfloat162_rn(hi);
                    *(__nv_bfloat162*)(g_kvb + (size_t)m * 144 + gc - 80) = blo;
                    *(__nv_bfloat162*)(g_kvb + (size_t)(m + 8) * 144 + gc - 80) = bhi;
                }
            }
        }
    } else {
        int bidx = m0 >> 12;
        int pixbase = (m0 & 4095) + wm * 32;
        #pragma unroll
        for (int nt = 0; nt < 4; nt++) {
            int oc = by * 128 + wn * 32 + nt * 8 + tg * 2;
            float inv0 = rsqrtf(rvar[oc] + 1e-5f);
            float sc0 = gamma[oc] * inv0;
            float sh0 = beta[oc] - rmean[oc] * sc0;
            float inv1 = rsqrtf(rvar[oc + 1] + 1e-5f);
            float sc1 = gamma[oc + 1] * inv1;
            float sh1 = beta[oc + 1] - rmean[oc + 1] * sc1;
            float* o0 = out + ((size_t)(bidx * 256 + oc)) * NPIX;
            float* o1 = out + ((size_t)(bidx * 256 + oc + 1)) * NPIX;
            #pragma unroll
            for (int mt = 0; mt < 2; mt++) {
                int pix = pixbase + mt * 16 + gid;
                o0[pix]     = fmaxf(d[mt][nt][0] * sc0 + sh0, 0.f);
                o1[pix]     = fmaxf(d[mt][nt][1] * sc1 + sh1, 0.f);
                o0[pix + 8] = fmaxf(d[mt][nt][2] * sc0 + sh0, 0.f);
                o1[pix + 8] = fmaxf(d[mt][nt][3] * sc1 + sh1, 0.f);
            }
        }
    }
}

// ---------------- deformable point attention (R11 exact) -----------------
__global__ void __launch_bounds__(512, 3) attention_kernel()
{
    __shared__ int    sIdx[8][128];
    __shared__ float  sW  [8][128];
    __shared__ float  sLogit[8][32];
    __shared__ float  sAttn[8][32];
    __shared__ float4 sPart[8][32];
    int tid = threadIdx.x;
    int warp = tid >> 5, lane = tid & 31;
    int q = warp & 7, half = warp >> 3;
    int m = blockIdx.x * 8 + q;
    int b = m >> 12;
    int n = m & (NPIX - 1);

    const float* row = g_qoff + (size_t)m * 80;

    float2 d = *(const float2*)(row + 16 + 2 * lane);
    float sx = (float)(n & 63) + d.x;
    float sy = (float)(n >> 6) + d.y;
    float x0f = floorf(sx), y0f = floorf(sy);
    float wx = sx - x0f,    wy = sy - y0f;
    int ix0 = min(max((int)x0f, 0), WL - 1);
    int ix1 = min(max((int)x0f + 1, 0), WL - 1);
    int iy0 = min(max((int)y0f, 0), HL - 1);
    int iy1 = min(max((int)y0f + 1, 0), HL - 1);
    int g00 = (iy0 * WL + ix0) * 288, g01 = (iy0 * WL + ix1) * 288;
    int g10 = (iy1 * WL + ix0) * 288, g11 = (iy1 * WL + ix1) * 288;
    float w00 = (1.f - wx) * (1.f - wy), w01 = wx * (1.f - wy);
    float w10 = (1.f - wx) * wy,         w11 = wx * wy;

    int cq = lane & 3;
    int oct = lane >> 2;
    float4 qv = *(const float4*)(row + 4 * cq);
    const char* kvB = (const char*)(g_kvb + (size_t)b * NPIX * 144);

    #pragma unroll
    for (int gi = 0; gi < 2; gi++) {
        int g = half * 2 + gi;
        int src = oct + 8 * g;
        int G0 = __shfl_sync(0xffffffffu, g00, src);
        int G1 = __shfl_sync(0xffffffffu, g01, src);
        int G2 = __shfl_sync(0xffffffffu, g10, src);
        int G3 = __shfl_sync(0xffffffffu, g11, src);
        float W0 = __shfl_sync(0xffffffffu, w00, src);
        float W1 = __shfl_sync(0xffffffffu, w01, src);
        float W2 = __shfl_sync(0xffffffffu, w10, src);
        float W3 = __shfl_sync(0xffffffffu, w11, src);
        uint2 kp0 = *(const uint2*)(kvB + G0 + cq * 8);
        uint2 kp1 = *(const uint2*)(kvB + G1 + cq * 8);
        uint2 kp2 = *(const uint2*)(kvB + G2 + cq * 8);
        uint2 kp3 = *(const uint2*)(kvB + G3 + cq * 8);
        float ksx = W0 * bfu_lo(kp0.x) + W1 * bfu_lo(kp1.x) + W2 * bfu_lo(kp2.x) + W3 * bfu_lo(kp3.x);
        float ksy = W0 * bfu_hi(kp0.x) + W1 * bfu_hi(kp1.x) + W2 * bfu_hi(kp2.x) + W3 * bfu_hi(kp3.x);
        float ksz = W0 * bfu_lo(kp0.y) + W1 * bfu_lo(kp1.y) + W2 * bfu_lo(kp2.y) + W3 * bfu_lo(kp3.y);
        float ksw = W0 * bfu_hi(kp0.y) + W1 * bfu_hi(kp1.y) + W2 * bfu_hi(kp2.y) + W3 * bfu_hi(kp3.y);
        float part = qv.x * ksx + qv.y * ksy + qv.z * ksz + qv.w * ksw;
        part += __shfl_xor_sync(0xffffffffu, part, 1);
        part += __shfl_xor_sync(0xffffffffu, part, 2);
        if (cq == 0) sLogit[q][src] = part * 0.25f;   // 1/sqrt(16)
        int   Gq = (cq == 0) ? G0 : (cq == 1) ? G1 : (cq == 2) ? G2 : G3;
        float Wq = (cq == 0) ? W0 : (cq == 1) ? W1 : (cq == 2) ? W2 : W3;
        sIdx[q][src * 4 + cq] = Gq;
        sW  [q][src * 4 + cq] = Wq;
    }
    __syncthreads();

    float lg = sLogit[q][lane];
    float mx = lg;
    #pragma unroll
    for (int s = 16; s; s >>= 1) mx = fmaxf(mx, __shfl_xor_sync(0xffffffffu, mx, s));
    float e = __expf(lg - mx);
    float sum = e;
    #pragma unroll
    for (int s = 16; s; s >>= 1) sum += __shfl_xor_sync(0xffffffffu, sum, s);
    sAttn[q][lane] = e / sum;
    __syncwarp();

    int base = half * 64;
    uint32_t* sWp = (uint32_t*)&sW[q][0];
    #pragma unroll
    for (int j = 0; j < 2; j++) {
        int tt = base + j * 32 + lane;
        float w = sW[q][tt] * sAttn[q][tt >> 2];
        sWp[tt] = bf16x2_dup(w);
    }
    __syncwarp();

    float4 acc = make_float4(0.f, 0.f, 0.f, 0.f);
    int loff = 32 + lane * 8;   // v starts at byte 32 of the row
    #pragma unroll 4
    for (int t = 0; t < 64; t += 4) {
        int tt = base + t;
        int4  i4  = *(const int4*)&sIdx[q][tt];
        uint4 wp4 = *(const uint4*)&sWp[tt];
        uint2 p0 = *(const uint2*)(kvB + i4.x + loff);
        uint2 p1 = *(const uint2*)(kvB + i4.y + loff);
        uint2 p2 = *(const uint2*)(kvB + i4.z + loff);
        uint2 p3 = *(const uint2*)(kvB + i4.w + loff);
        uint32_t a0 = 0, a1 = 0;
        hfma2b(a0, wp4.x, p0.x);  hfma2b(a1, wp4.x, p0.y);
        hfma2b(a0, wp4.y, p1.x);  hfma2b(a1, wp4.y, p1.y);
        hfma2b(a0, wp4.z, p2.x);  hfma2b(a1, wp4.z, p2.y);
        hfma2b(a0, wp4.w, p3.x);  hfma2b(a1, wp4.w, p3.y);
        acc.x += bfu_lo(a0);  acc.y += bfu_hi(a0);
        acc.z += bfu_lo(a1);  acc.w += bfu_hi(a1);
    }
    if (half) sPart[q][lane] = acc;
    __syncthreads();
    if (!half) {
        float4 p = sPart[q][lane];
        acc.x += p.x; acc.y += p.y; acc.z += p.z; acc.w += p.w;
        size_t obase = (size_t)m * 128 + lane * 4;
        __nv_bfloat16 hv[4], lv[4];
        split_bf16(acc.x, hv[0], lv[0]);
        split_bf16(acc.y, hv[1], lv[1]);
        split_bf16(acc.z, hv[2], lv[2]);
        split_bf16(acc.w, hv[3], lv[3]);
        *(uint2*)&g_attn_h[obase] = *(uint2*)hv;
        *(uint2*)&g_attn_l[obase] = *(uint2*)lv;
    }
}

// ---------------- launch ------------------------------------------------
extern "C" void kernel_launch(void* const* d_in, const int* in_sizes, int n_in,
                              void* d_out, int out_size) {
    const float* low   = (const float*)d_in[0];
    const float* high  = (const float*)d_in[1];
    const float* W1    = (const float*)d_in[2];
    const float* b1    = (const float*)d_in[3];
    const float* W2    = (const float*)d_in[4];
    const float* b2    = (const float*)d_in[5];
    const float* Wq    = (const float*)d_in[6];
    const float* bq    = (const float*)d_in[7];
    const float* Wk    = (const float*)d_in[8];
    const float* bk    = (const float*)d_in[9];
    const float* Wv    = (const float*)d_in[10];
    const float* bv    = (const float*)d_in[11];
    const float* Woff  = (const float*)d_in[12];
    const float* boff  = (const float*)d_in[13];
    const float* Wb    = (const float*)d_in[14];
    const float* gamma = (const float*)d_in[15];
    const float* beta  = (const float*)d_in[16];
    const float* rmean = (const float*)d_in[17];
    const float* rvar  = (const float*)d_in[18];
    float* out = (float*)d_out;

    cudaFuncSetAttribute(hmma_kernel, cudaFuncAttributeMaxDynamicSharedMemorySize, HMMA_SMEM_2);

    prep_kernel<<<4160, 256>>>(high, low, W1, W2, Wb,
                               Wq, bq, Woff, boff, Wk, bk, Wv, bv);
    hmma_kernel<<<dim3(128, 2), 256, HMMA_SMEM_1>>>(
        0, b1, b2, nullptr, nullptr, nullptr, nullptr, nullptr);
    hmma_kernel<<<dim3(128, 2), 256, HMMA_SMEM_1>>>(
        1, nullptr, nullptr, nullptr, nullptr, nullptr, nullptr, nullptr);
    attention_kernel<<<MTOT / 8, 512>>>();
    hmma_kernel<<<dim3(128, 2), 256, HMMA_SMEM_2>>>(
        2, nullptr, nullptr, gamma, beta, rmean, rvar, out);
}

// round 16
// speedup vs baseline: 1.1868x; 1.0458x over previous
#include <cuda_runtime.h>
#include <cuda_bf16.h>
#include <math.h>
#include <stdint.h>

// ---------------- problem constants ----------------
#define NB   2
#define CH   256
#define INC  128
#define ITC  16
#define NPT  32
#define HL   64
#define WL   64
#define NPIX 4096
#define HH   32
#define WH   32
#define MTOT (NB * NPIX)   // 8192 rows (batch folded into M)

// ---------------- scratch (__device__ globals, no allocs) ----------------
__device__ __align__(16) __nv_bfloat16 g_c1h[MTOT * 512];  // cat1 hi
__device__ __align__(16) __nv_bfloat16 g_c1l[MTOT * 512];  // cat1 lo (only cols 0-255 used)
__device__ __align__(16) __nv_bfloat16 g_fh [MTOT * 256];  // qf|vf (bf16, single)
__device__ __align__(16) float g_qoff[MTOT * 80];          // q[16] | off[64] fp32
__device__ __align__(16) __nv_bfloat16 g_kvb[MTOT * 144];  // k[16] | v[128] bf16 (288B rows)
__device__ __align__(16) __nv_bfloat16 g_attn[MTOT * 128]; // attention output, single bf16
__device__ __align__(16) __nv_bfloat16 g_W1h[128 * 512];
__device__ __align__(16) __nv_bfloat16 g_W2h[128 * 256];
__device__ __align__(16) __nv_bfloat16 g_Wbh[256 * 384], g_Wbl[256 * 384];
__device__ __align__(16) __nv_bfloat16 g_Wgh[256 * 256];   // block-diag [q;off;k;v]
__device__ float g_bg[256];

// ---------------- mma.sync helpers ----------------
__device__ __forceinline__ uint32_t smem_u32(const void* p) {
    uint32_t a;
    asm("{ .reg .u64 t; cvta.to.shared.u64 t, %1; cvt.u32.u64 %0, t; }" : "=r"(a) : "l"(p));
    return a;
}
__device__ __forceinline__ void ldm_x4(uint32_t* r, uint32_t addr) {
    asm volatile("ldmatrix.sync.aligned.m8n8.x4.shared.b16 {%0,%1,%2,%3}, [%4];"
        : "=r"(r[0]), "=r"(r[1]), "=r"(r[2]), "=r"(r[3]) : "r"(addr));
}
__device__ __forceinline__ void mma_bf16(float* d, const uint32_t* a, const uint32_t* b) {
    asm volatile("mma.sync.aligned.m16n8k16.row.col.f32.bf16.bf16.f32 "
        "{%0,%1,%2,%3}, {%4,%5,%6,%7}, {%8,%9}, {%0,%1,%2,%3};"
        : "+f"(d[0]), "+f"(d[1]), "+f"(d[2]), "+f"(d[3])
        : "r"(a[0]), "r"(a[1]), "r"(a[2]), "r"(a[3]), "r"(b[0]), "r"(b[1]));
}

__device__ __forceinline__ void split_bf16(float x, __nv_bfloat16& h, __nv_bfloat16& l) {
    h = __float2bfloat16(x);
    l = __float2bfloat16(x - __bfloat162float(h));
}
// bf16x2 word -> two fp32 via pure bit ops (exact; no CVT pipe)
__device__ __forceinline__ float bfu_lo(uint32_t u) { return __uint_as_float(u << 16); }
__device__ __forceinline__ float bfu_hi(uint32_t u) { return __uint_as_float(u & 0xffff0000u); }
// packed bf16x2 fma: d += a*b (HFMA2.BF16_V2, fma pipe)
__device__ __forceinline__ void hfma2b(uint32_t& d, uint32_t a, uint32_t b) {
    asm("fma.rn.bf16x2 %0, %1, %2, %0;" : "+r"(d) : "r"(a), "r"(b));
}
// duplicate fp32 into both lanes of a bf16x2 word
__device__ __forceinline__ uint32_t bf16x2_dup(float x) {
    uint32_t r;
    asm("cvt.rn.bf16x2.f32 %0, %1, %1;" : "=r"(r) : "f"(x));
    return r;
}

// ---------------- prep: upsample + transpose -> bf16 splits; weight packing --
__global__ void __launch_bounds__(256) prep_kernel(
    const float* __restrict__ high, const float* __restrict__ low,
    const float* __restrict__ W1, const float* __restrict__ W2,
    const float* __restrict__ Wb,
    const float* __restrict__ Wq, const float* __restrict__ bq,
    const float* __restrict__ Woff, const float* __restrict__ boff,
    const float* __restrict__ Wk, const float* __restrict__ bk,
    const float* __restrict__ Wv, const float* __restrict__ bv)
{
    int blk = blockIdx.x;
    int tid = threadIdx.x;

    if (blk >= 4096) {
        for (int e = (blk - 4096) * 256 + tid; e < 262400; e += 16384) {
            if (e < 65536) {
                g_W1h[e] = __float2bfloat16(W1[e]);
            } else if (e < 98304) {
                int t = e - 65536;
                g_W2h[t] = __float2bfloat16(W2[t]);
            } else if (e < 196608) {
                int t = e - 98304;
                split_bf16(Wb[t], g_Wbh[t], g_Wbl[t]);
            } else if (e < 262144) {
                int t = e - 196608;
                int r = t >> 8, k = t & 255;
                float v = 0.f;
                if (r < 16)       { if (k < 128)  v = Wq[r * 128 + k]; }
                else if (r < 80)  { if (k < 128)  v = Woff[(r - 16) * 128 + k]; }
                else if (r < 96)  { if (k >= 128) v = Wk[(r - 80) * 128 + k - 128]; }
                else if (r < 224) { if (k >= 128) v = Wv[(r - 96) * 128 + k - 128]; }
                g_Wgh[t] = __float2bfloat16(v);
            } else {
                int i = e - 262144;
                float v = 0.f;
                if (i < 16)       v = bq[i];
                else if (i < 80)  v = boff[i - 16];
                else if (i < 96)  v = bk[i - 80];
                else if (i < 224) v = bv[i - 96];
                g_bg[i] = v;
            }
        }
        return;
    }

    int part = blk >> 11;          // 0: high_up, 1: low
    int r = blk & 2047;
    int b = r >> 10;
    int r2 = r & 1023;
    int pt = r2 >> 3;
    int ct = r2 & 7;
    int p0 = pt * 32;
    int c0 = ct * 32;

    __shared__ float s[32][33];
    int px = tid & 31;
    int cq = tid >> 5;

    if (part == 1) {
        #pragma unroll
        for (int i = 0; i < 4; i++) {
            int c = cq * 4 + i;
            s[c][px] = low[((size_t)(b * CH + c0 + c)) * NPIX + p0 + px];
        }
    } else {
        int y = p0 >> 6;
        int xb = p0 & 63;
        float fy = y * 0.5f - 0.25f;
        float y0f = floorf(fy);
        float wy = fy - y0f;
        int iy0 = min(max((int)y0f, 0), HH - 1);
        int iy1 = min(max((int)y0f + 1, 0), HH - 1);
        int x = xb + px;
        float fx = x * 0.5f - 0.25f;
        float x0f = floorf(fx);
        float wx = fx - x0f;
        int ix0 = min(max((int)x0f, 0), WH - 1);
        int ix1 = min(max((int)x0f + 1, 0), WH - 1);
        #pragma unroll
        for (int i = 0; i < 4; i++) {
            int c = cq * 4 + i;
            const float* src = high + ((size_t)(b * CH + c0 + c)) * (HH * WH);
            float v00 = src[iy0 * WH + ix0], v01 = src[iy0 * WH + ix1];
            float v10 = src[iy1 * WH + ix0], v11 = src[iy1 * WH + ix1];
            s[c][px] = (1.f - wx) * (1.f - wy) * v00 + wx * (1.f - wy) * v01
                     + (1.f - wx) * wy * v10 + wx * wy * v11;
        }
    }
    __syncthreads();

    // write out: 2 channels per store (bf16x2); lo split only for high_up half
    int cc = (tid & 15) * 2;
    int pq = tid >> 4;
    int base_c = (part == 0 ? c0 : 256 + c0) + cc;
    #pragma unroll
    for (int i = 0; i < 2; i++) {
        int pp = pq * 2 + i;
        size_t idx = ((size_t)(b * NPIX + p0 + pp)) * 512 + base_c;
        if (part == 0) {
            __nv_bfloat16 h0, l0, h1, l1;
            split_bf16(s[cc][pp],     h0, l0);
            split_bf16(s[cc + 1][pp], h1, l1);
            __nv_bfloat162 hp = {h0, h1}, lp = {l0, l1};
            *(__nv_bfloat162*)&g_c1h[idx] = hp;
            *(__nv_bfloat162*)&g_c1l[idx] = lp;
        } else {
            float2 v = make_float2(s[cc][pp], s[cc + 1][pp]);
            *(__nv_bfloat162*)&g_c1h[idx] = __float22bfloat162_rn(v);
        }
    }
}

// ---------------- bf16 mma.sync GEMM ------------------------------------
// stages 0,1: single-term bf16.  stage 2: bf16x3 on c1 chunks, single on attn.
// Block 64(M) x 128(N), 8 warps (2x4), warp tile 32x32, K-chunk 32,
// double-buffered smem, pitch 40 bf16.
#define PITCH 40
#define A_ELEMS (64 * PITCH)
#define B_ELEMS (128 * PITCH)
#define BUF1 (A_ELEMS + B_ELEMS)       // single-term buffer: 7680 elems
#define BUF2 (2 * (A_ELEMS + B_ELEMS)) // full buffer: 15360 elems
#define HMMA_SMEM_1 (2 * BUF1 * 2)     // 30720 B
#define HMMA_SMEM_2 (2 * BUF2 * 2)     // 61440 B

__global__ void __launch_bounds__(256) hmma_kernel(
    int stage,
    const float* __restrict__ bias0, const float* __restrict__ bias1,
    const float* __restrict__ gamma, const float* __restrict__ beta,
    const float* __restrict__ rmean, const float* __restrict__ rvar,
    float* __restrict__ out)
{
    extern __shared__ __nv_bfloat16 sm[];
    int tid = threadIdx.x;
    int wid = tid >> 5, lane = tid & 31;
    int wm = wid >> 2, wn = wid & 3;       // 2 x 4 warp grid, warp tile 32x32
    int gid = lane >> 2, tg = lane & 3;
    int m0 = blockIdx.x * 64;
    int by = blockIdx.y;

    int bufElems = (stage == 2) ? BUF2 : BUF1;

    int K, ldb;
    const __nv_bfloat16 *Bh, *Bl = nullptr;
    const float* bias = nullptr;
    if (stage == 0) {
        if (by == 0) { K = 512; Bh = g_W1h; ldb = 512; bias = bias0; }
        else         { K = 256; Bh = g_W2h; ldb = 256; bias = bias1; }
    } else if (stage == 1) {
        K = 256; ldb = 256;
        Bh = g_Wgh + (size_t)by * 128 * 256;
    } else {
        K = 384; ldb = 384;
        Bh = g_Wbh + (size_t)by * 128 * 384;
        Bl = g_Wbl + (size_t)by * 128 * 384;
    }
    int nc = K >> 5;

    // stage2: chunks 0-3 = attn (single term), 4-11 = c1 (3 terms)
    auto is_full = [&](int c) { return (stage == 2) && (c >= 4); };

    float d[2][4][4];
    #pragma unroll
    for (int i = 0; i < 2; i++)
        #pragma unroll
        for (int j = 0; j < 4; j++)
            #pragma unroll
            for (int k = 0; k < 4; k++) d[i][j][k] = 0.f;

    int seg = tid & 3;
    int r0 = tid >> 2;         // 0..63

    uint4 stg[6];
    auto ldg_chunk = [&](int c) {
        const __nv_bfloat16 *Ah_src, *Al_src = nullptr;
        int lda, colA;
        if (stage == 0)      { Ah_src = g_c1h; lda = 512; colA = c * 32; }
        else if (stage == 1) { Ah_src = g_fh;  lda = 256; colA = c * 32; }
        else if (c < 4)      { Ah_src = g_attn; lda = 128; colA = c * 32; }
        else                 { Ah_src = g_c1h; Al_src = g_c1l; lda = 512; colA = (c - 4) * 32; }
        stg[0] = *(const uint4*)(Ah_src + (size_t)(m0 + r0) * lda + colA + seg * 8);
        stg[1] = *(const uint4*)(Bh + (size_t)r0 * ldb + c * 32 + seg * 8);
        stg[2] = *(const uint4*)(Bh + (size_t)(r0 + 64) * ldb + c * 32 + seg * 8);
        if (is_full(c)) {
            stg[3] = *(const uint4*)(Al_src + (size_t)(m0 + r0) * lda + colA + seg * 8);
            stg[4] = *(const uint4*)(Bl + (size_t)r0 * ldb + c * 32 + seg * 8);
            stg[5] = *(const uint4*)(Bl + (size_t)(r0 + 64) * ldb + c * 32 + seg * 8);
        }
    };
    // buffer layout: [Ah | Bh | (Al) | (Bl)]
    auto sts_chunk = [&](int buf, bool fullc) {
        __nv_bfloat16* base = sm + buf * bufElems;
        *(uint4*)(base + r0 * PITCH + seg * 8)                      = stg[0];
        *(uint4*)(base + A_ELEMS + r0 * PITCH + seg * 8)            = stg[1];
        *(uint4*)(base + A_ELEMS + (r0 + 64) * PITCH + seg * 8)     = stg[2];
        if (fullc) {
            __nv_bfloat16* b2 = base + A_ELEMS + B_ELEMS;
            *(uint4*)(b2 + r0 * PITCH + seg * 8)                    = stg[3];
            *(uint4*)(b2 + A_ELEMS + r0 * PITCH + seg * 8)          = stg[4];
            *(uint4*)(b2 + A_ELEMS + (r0 + 64) * PITCH + seg * 8)   = stg[5];
        }
    };

    uint32_t sm0 = smem_u32(sm);
    auto compute = [&](int buf, bool fullc) {
        uint32_t base = sm0 + (buf * bufElems) * 2;
        uint32_t aAh = base;
        uint32_t aBh = base + A_ELEMS * 2;
        uint32_t aAl = base + (A_ELEMS + B_ELEMS) * 2;
        uint32_t aBl = aAl + A_ELEMS * 2;
        #pragma unroll
        for (int h = 0; h < 2; h++) {
            uint32_t ah[2][4], al[2][4], bh[2][4], bl[2][4];
            uint32_t a_off = (uint32_t)((wm * 32 + (lane & 15)) * (PITCH * 2)
                                        + h * 32 + (lane >> 4) * 16);
            int q8 = lane >> 3;
            uint32_t b_off = (uint32_t)((wn * 32 + (q8 >> 1) * 8 + (lane & 7)) * (PITCH * 2)
                                        + h * 32 + (q8 & 1) * 16);
            #pragma unroll
            for (int mt = 0; mt < 2; mt++)
                ldm_x4(ah[mt], aAh + a_off + mt * 16 * (PITCH * 2));
            ldm_x4(bh[0], aBh + b_off);
            ldm_x4(bh[1], aBh + b_off + 16 * (PITCH * 2));
            if (fullc) {
                #pragma unroll
                for (int mt = 0; mt < 2; mt++)
                    ldm_x4(al[mt], aAl + a_off + mt * 16 * (PITCH * 2));
                ldm_x4(bl[0], aBl + b_off);
                ldm_x4(bl[1], aBl + b_off + 16 * (PITCH * 2));
            }
            #pragma unroll
            for (int mt = 0; mt < 2; mt++) {
                #pragma unroll
                for (int nt = 0; nt < 4; nt++) {
                    const uint32_t* pbh = &bh[nt >> 1][(nt & 1) * 2];
                    mma_bf16(d[mt][nt], ah[mt], pbh);
                    if (fullc) {
                        const uint32_t* pbl = &bl[nt >> 1][(nt & 1) * 2];
                        mma_bf16(d[mt][nt], ah[mt], pbl);
                        mma_bf16(d[mt][nt], al[mt], pbh);
                    }
                }
            }
        }
    };

    ldg_chunk(0);
    sts_chunk(0, is_full(0));
    __syncthreads();
    for (int c = 0; c < nc; c++) {
        if (c + 1 < nc) ldg_chunk(c + 1);
        compute(c & 1, is_full(c));
        if (c + 1 < nc) {
            sts_chunk((c + 1) & 1, is_full(c + 1));
            __syncthreads();
        }
    }

    if (stage == 0) {
        #pragma unroll
        for (int mt = 0; mt < 2; mt++) {
            int m = m0 + wm * 32 + mt * 16 + gid;
            #pragma unroll
            for (int nt = 0; nt < 4; nt++) {
                int cc = wn * 32 + nt * 8 + tg * 2;
                int gcol = by * 128 + cc;
                float bx = bias[cc], byv = bias[cc + 1];
                float2 lo = make_float2(d[mt][nt][0] + bx, d[mt][nt][1] + byv);
                float2 hi = make_float2(d[mt][nt][2] + bx, d[mt][nt][3] + byv);
                *(__nv_bfloat162*)&g_fh[(size_t)m * 256 + gcol] = __float22bfloat162_rn(lo);
                *(__nv_bfloat162*)&g_fh[(size_t)(m + 8) * 256 + gcol] = __float22bfloat162_rn(hi);
            }
        }
    } else if (stage == 1) {
        #pragma unroll
        for (int mt = 0; mt < 2; mt++) {
            int m = m0 + wm * 32 + mt * 16 + gid;
            #pragma unroll
            for (int nt = 0; nt < 4; nt++) {
                int gc = by * 128 + wn * 32 + nt * 8 + tg * 2;
                if (gc >= 224) continue;
                float bx = g_bg[gc], byv = g_bg[gc + 1];
                float2 lo = make_float2(d[mt][nt][0] + bx, d[mt][nt][1] + byv);
                float2 hi = make_float2(d[mt][nt][2] + bx, d[mt][nt][3] + byv);
                if (gc < 80) {
                    *(float2*)(g_qoff + (size_t)m * 80 + gc) = lo;
                    *(float2*)(g_qoff + (size_t)(m + 8) * 80 + gc) = hi;
                } else {
                    __nv_bfloat162 blo = __float22bfloat162_rn(lo);
                    __nv_bfloat162 bhi = __float22bfloat162_rn(hi);
                    *(__nv_bfloat162*)(g_kvb + (size_t)m * 144 + gc - 80) = blo;
                    *(__nv_bfloat162*)(g_kvb + (size_t)(m + 8) * 144 + gc - 80) = bhi;
                }
            }
        }
    } else {
        int bidx = m0 >> 12;
        int pixbase = (m0 & 4095) + wm * 32;
        #pragma unroll
        for (int nt = 0; nt < 4; nt++) {
            int oc = by * 128 + wn * 32 + nt * 8 + tg * 2;
            float inv0 = rsqrtf(rvar[oc] + 1e-5f);
            float sc0 = gamma[oc] * inv0;
            float sh0 = beta[oc] - rmean[oc] * sc0;
            float inv1 = rsqrtf(rvar[oc + 1] + 1e-5f);
            float sc1 = gamma[oc + 1] * inv1;
            float sh1 = beta[oc + 1] - rmean[oc + 1] * sc1;
            float* o0 = out + ((size_t)(bidx * 256 + oc)) * NPIX;
            float* o1 = out + ((size_t)(bidx * 256 + oc + 1)) * NPIX;
            #pragma unroll
            for (int mt = 0; mt < 2; mt++) {
                int pix = pixbase + mt * 16 + gid;
                o0[pix]     = fmaxf(d[mt][nt][0] * sc0 + sh0, 0.f);
                o1[pix]     = fmaxf(d[mt][nt][1] * sc1 + sh1, 0.f);
                o0[pix + 8] = fmaxf(d[mt][nt][2] * sc0 + sh0, 0.f);
                o1[pix + 8] = fmaxf(d[mt][nt][3] * sc1 + sh1, 0.f);
            }
        }
    }
}

// ---------------- deformable point attention (R11 core, bf16 out) --------
__global__ void __launch_bounds__(512, 3) attention_kernel()
{
    __shared__ int    sIdx[8][128];
    __shared__ float  sW  [8][128];
    __shared__ float  sLogit[8][32];
    __shared__ float  sAttn[8][32];
    __shared__ float4 sPart[8][32];
    int tid = threadIdx.x;
    int warp = tid >> 5, lane = tid & 31;
    int q = warp & 7, half = warp >> 3;
    int m = blockIdx.x * 8 + q;
    int b = m >> 12;
    int n = m & (NPIX - 1);

    const float* row = g_qoff + (size_t)m * 80;

    float2 d = *(const float2*)(row + 16 + 2 * lane);
    float sx = (float)(n & 63) + d.x;
    float sy = (float)(n >> 6) + d.y;
    float x0f = floorf(sx), y0f = floorf(sy);
    float wx = sx - x0f,    wy = sy - y0f;
    int ix0 = min(max((int)x0f, 0), WL - 1);
    int ix1 = min(max((int)x0f + 1, 0), WL - 1);
    int iy0 = min(max((int)y0f, 0), HL - 1);
    int iy1 = min(max((int)y0f + 1, 0), HL - 1);
    int g00 = (iy0 * WL + ix0) * 288, g01 = (iy0 * WL + ix1) * 288;
    int g10 = (iy1 * WL + ix0) * 288, g11 = (iy1 * WL + ix1) * 288;
    float w00 = (1.f - wx) * (1.f - wy), w01 = wx * (1.f - wy);
    float w10 = (1.f - wx) * wy,         w11 = wx * wy;

    int cq = lane & 3;
    int oct = lane >> 2;
    float4 qv = *(const float4*)(row + 4 * cq);
    const char* kvB = (const char*)(g_kvb + (size_t)b * NPIX * 144);

    #pragma unroll
    for (int gi = 0; gi < 2; gi++) {
        int g = half * 2 + gi;
        int src = oct + 8 * g;
        int G0 = __shfl_sync(0xffffffffu, g00, src);
        int G1 = __shfl_sync(0xffffffffu, g01, src);
        int G2 = __shfl_sync(0xffffffffu, g10, src);
        int G3 = __shfl_sync(0xffffffffu, g11, src);
        float W0 = __shfl_sync(0xffffffffu, w00, src);
        float W1 = __shfl_sync(0xffffffffu, w01, src);
        float W2 = __shfl_sync(0xffffffffu, w10, src);
        float W3 = __shfl_sync(0xffffffffu, w11, src);
        uint2 kp0 = *(const uint2*)(kvB + G0 + cq * 8);
        uint2 kp1 = *(const uint2*)(kvB + G1 + cq * 8);
        uint2 kp2 = *(const uint2*)(kvB + G2 + cq * 8);
        uint2 kp3 = *(const uint2*)(kvB + G3 + cq * 8);
        float ksx = W0 * bfu_lo(kp0.x) + W1 * bfu_lo(kp1.x) + W2 * bfu_lo(kp2.x) + W3 * bfu_lo(kp3.x);
        float ksy = W0 * bfu_hi(kp0.x) + W1 * bfu_hi(kp1.x) + W2 * bfu_hi(kp2.x) + W3 * bfu_hi(kp3.x);
        float ksz = W0 * bfu_lo(kp0.y) + W1 * bfu_lo(kp1.y) + W2 * bfu_lo(kp2.y) + W3 * bfu_lo(kp3.y);
        float ksw = W0 * bfu_hi(kp0.y) + W1 * bfu_hi(kp1.y) + W2 * bfu_hi(kp2.y) + W3 * bfu_hi(kp3.y);
        float part = qv.x * ksx + qv.y * ksy + qv.z * ksz + qv.w * ksw;
        part += __shfl_xor_sync(0xffffffffu, part, 1);
        part += __shfl_xor_sync(0xffffffffu, part, 2);
        if (cq == 0) sLogit[q][src] = part * 0.25f;   // 1/sqrt(16)
        int   Gq = (cq == 0) ? G0 : (cq == 1) ? G1 : (cq == 2) ? G2 : G3;
        float Wq = (cq == 0) ? W0 : (cq == 1) ? W1 : (cq == 2) ? W2 : W3;
        sIdx[q][src * 4 + cq] = Gq;
        sW  [q][src * 4 + cq] = Wq;
    }
    __syncthreads();

    float lg = sLogit[q][lane];
    float mx = lg;
    #pragma unroll
    for (int s = 16; s; s >>= 1) mx = fmaxf(mx, __shfl_xor_sync(0xffffffffu, mx, s));
    float e = __expf(lg - mx);
    float sum = e;
    #pragma unroll
    for (int s = 16; s; s >>= 1) sum += __shfl_xor_sync(0xffffffffu, sum, s);
    sAttn[q][lane] = e / sum;
    __syncwarp();

    int base = half * 64;
    uint32_t* sWp = (uint32_t*)&sW[q][0];
    #pragma unroll
    for (int j = 0; j < 2; j++) {
        int tt = base + j * 32 + lane;
        float w = sW[q][tt] * sAttn[q][tt >> 2];
        sWp[tt] = bf16x2_dup(w);
    }
    __syncwarp();

    float4 acc = make_float4(0.f, 0.f, 0.f, 0.f);
    int loff = 32 + lane * 8;   // v starts at byte 32 of the row
    #pragma unroll 4
    for (int t = 0; t < 64; t += 4) {
        int tt = base + t;
        int4  i4  = *(const int4*)&sIdx[q][tt];
        uint4 wp4 = *(const uint4*)&sWp[tt];
        uint2 p0 = *(const uint2*)(kvB + i4.x + loff);
        uint2 p1 = *(const uint2*)(kvB + i4.y + loff);
        uint2 p2 = *(const uint2*)(kvB + i4.z + loff);
        uint2 p3 = *(const uint2*)(kvB + i4.w + loff);
        uint32_t a0 = 0, a1 = 0;
        hfma2b(a0, wp4.x, p0.x);  hfma2b(a1, wp4.x, p0.y);
        hfma2b(a0, wp4.y, p1.x);  hfma2b(a1, wp4.y, p1.y);
        hfma2b(a0, wp4.z, p2.x);  hfma2b(a1, wp4.z, p2.y);
        hfma2b(a0, wp4.w, p3.x);  hfma2b(a1, wp4.w, p3.y);
        acc.x += bfu_lo(a0);  acc.y += bfu_hi(a0);
        acc.z += bfu_lo(a1);  acc.w += bfu_hi(a1);
    }
    if (half) sPart[q][lane] = acc;
    __syncthreads();
    if (!half) {
        float4 p = sPart[q][lane];
        acc.x += p.x; acc.y += p.y; acc.z += p.z; acc.w += p.w;
        size_t obase = (size_t)m * 128 + lane * 4;
        __nv_bfloat162 v0 = __float22bfloat162_rn(make_float2(acc.x, acc.y));
        __nv_bfloat162 v1 = __float22bfloat162_rn(make_float2(acc.z, acc.w));
        uint2 pk;
        pk.x = *(uint32_t*)&v0;
        pk.y = *(uint32_t*)&v1;
        *(uint2*)&g_attn[obase] = pk;
    }
}

// ---------------- launch ------------------------------------------------
extern "C" void kernel_launch(void* const* d_in, const int* in_sizes, int n_in,
                              void* d_out, int out_size) {
    const float* low   = (const float*)d_in[0];
    const float* high  = (const float*)d_in[1];
    const float* W1    = (const float*)d_in[2];
    const float* b1    = (const float*)d_in[3];
    const float* W2    = (const float*)d_in[4];
    const float* b2    = (const float*)d_in[5];
    const float* Wq    = (const float*)d_in[6];
    const float* bq    = (const float*)d_in[7];
    const float* Wk    = (const float*)d_in[8];
    const float* bk    = (const float*)d_in[9];
    const float* Wv    = (const float*)d_in[10];
    const float* bv    = (const float*)d_in[11];
    const float* Woff  = (const float*)d_in[12];
    const float* boff  = (const float*)d_in[13];
    const float* Wb    = (const float*)d_in[14];
    const float* gamma = (const float*)d_in[15];
    const float* beta  = (const float*)d_in[16];
    const float* rmean = (const float*)d_in[17];
    const float* rvar  = (const float*)d_in[18];
    float* out = (float*)d_out;

    cudaFuncSetAttribute(hmma_kernel, cudaFuncAttributeMaxDynamicSharedMemorySize, HMMA_SMEM_2);

    prep_kernel<<<4160, 256>>>(high, low, W1, W2, Wb,
                               Wq, bq, Woff, boff, Wk, bk, Wv, bv);
    hmma_kernel<<<dim3(128, 2), 256, HMMA_SMEM_1>>>(
        0, b1, b2, nullptr, nullptr, nullptr, nullptr, nullptr);
    hmma_kernel<<<dim3(128, 2), 256, HMMA_SMEM_1>>>(
        1, nullptr, nullptr, nullptr, nullptr, nullptr, nullptr, nullptr);
    attention_kernel<<<MTOT / 8, 512>>>();
    hmma_kernel<<<dim3(128, 2), 256, HMMA_SMEM_2>>>(
        2, nullptr, nullptr, gamma, beta, rmean, rvar, out);
}